// round 1
// baseline (speedup 1.0000x reference)
#include <cuda_runtime.h>
#include <cstddef>

#define NN  100000
#define DD  64
#define REX 8
#define RIM 4
#define EEX 2000000
#define EIM 1000000

// ---------------- scratch (static device globals; no allocation) ----------------
__device__ int   g_cnt_ex[NN * REX];
__device__ int   g_cnt_im[NN * RIM];
__device__ float g_inv_ex[NN * REX];
__device__ float g_inv_im[NN * RIM];
__device__ float g_ex_x1[NN * DD];
__device__ float g_im_x1[NN * DD];
__device__ float g_t_ex[NN * DD];
__device__ float g_t_im[NN * DD];
__device__ float g_ex_sum[NN * DD];
__device__ float g_im_sum[NN * DD];
__device__ float g_hidden[NN * DD];
__device__ float g_z_ex[REX * NN * DD];   // 204.8 MB
__device__ float g_z_im[RIM * NN * DD];   // 102.4 MB

// ---------------- helpers ----------------
__device__ __forceinline__ void red4(float* addr, float x, float y, float z, float w) {
    asm volatile("red.global.add.v4.f32 [%0], {%1, %2, %3, %4};"
                 :: "l"(addr), "f"(x), "f"(y), "f"(z), "f"(w) : "memory");
}

// ---------------- count per (dst, relation) ----------------
__global__ void count_kernel(const int* __restrict__ dst, const int* __restrict__ typ,
                             int E, int* __restrict__ cnt, int R) {
    int e = blockIdx.x * blockDim.x + threadIdx.x;
    if (e >= E) return;
    atomicAdd(&cnt[dst[e] * R + typ[e]], 1);
}

__global__ void make_inv(const int* __restrict__ cnt, float* __restrict__ inv, int n) {
    int i = blockIdx.x * blockDim.x + threadIdx.x;
    if (i >= n) return;
    int c = cnt[i];
    inv[i] = 1.0f / (float)(c > 1 ? c : 1);
}

// out[i] = root[i] + bias[i % 64]
__global__ void init_x1(const float* __restrict__ root, const float* __restrict__ bias,
                        float* __restrict__ out, int total) {
    int i = blockIdx.x * blockDim.x + threadIdx.x;
    if (i >= total) return;
    out[i] = root[i] + bias[i & 63];
}

// Per-edge scaled row scatter: out[dst] += table[(r*NN + src)*64 .. +64] * invc[dst*R + r]
// 16 threads per edge, float4 per thread, vectorized red.
__global__ void scatter_kernel(const float* __restrict__ table,
                               const int* __restrict__ src, const int* __restrict__ dst,
                               const int* __restrict__ typ, const float* __restrict__ invc,
                               int R, float* __restrict__ out, int E) {
    int idx  = blockIdx.x * blockDim.x + threadIdx.x;
    int e    = idx >> 4;
    int lane = idx & 15;
    if (e >= E) return;
    int s = src[e];
    int d = dst[e];
    int r = typ[e];
    float w = invc[d * R + r];
    const float4* row = reinterpret_cast<const float4*>(table) + ((size_t)r * NN + s) * 16 + lane;
    float4 v = *row;
    float* o = out + (size_t)d * DD + lane * 4;
    red4(o, v.x * w, v.y * w, v.z * w, v.w * w);
}

// ---------------- ATTITU fusion (warp per node) ----------------
__global__ void attitu_kernel(const float* __restrict__ ex1, const float* __restrict__ im1,
                              const float* __restrict__ w11, const float* __restrict__ b11,
                              const float* __restrict__ w12, const float* __restrict__ b12,
                              const float* __restrict__ w21, const float* __restrict__ b21,
                              const float* __restrict__ w22, const float* __restrict__ b22,
                              float* __restrict__ t_ex, float* __restrict__ t_im, int nnodes) {
    int g    = blockIdx.x * blockDim.x + threadIdx.x;
    int node = g >> 5;
    int lane = g & 31;
    if (node >= nnodes) return;
    const float* e1 = ex1 + (size_t)node * DD;
    const float* e2 = im1 + (size_t)node * DD;
    float a0 = e1[lane], a1 = e1[lane + 32];
    float c0 = e2[lane], c1 = e2[lane + 32];
    float p11 = a0 * w11[lane] + a1 * w11[lane + 32];
    float p12 = c0 * w12[lane] + c1 * w12[lane + 32];
    float p21 = a0 * w21[lane] + a1 * w21[lane + 32];
    float p22 = c0 * w22[lane] + c1 * w22[lane + 32];
    #pragma unroll
    for (int o = 16; o > 0; o >>= 1) {
        p11 += __shfl_xor_sync(0xFFFFFFFF, p11, o);
        p12 += __shfl_xor_sync(0xFFFFFFFF, p12, o);
        p21 += __shfl_xor_sync(0xFFFFFFFF, p21, o);
        p22 += __shfl_xor_sync(0xFFFFFFFF, p22, o);
    }
    // softmax over pair 1
    float l0 = p11 + b11[0], l1 = p12 + b12[0];
    float m = fmaxf(l0, l1);
    float q0 = expf(l0 - m), q1 = expf(l1 - m);
    float inv = 1.0f / (q0 + q1);
    float s0 = q0 * inv, s1 = q1 * inv;
    t_ex[(size_t)node * DD + lane]      = s0 * a0 + s1 * c0;
    t_ex[(size_t)node * DD + lane + 32] = s0 * a1 + s1 * c1;
    // softmax over pair 2
    float u0 = p21 + b21[0], u1 = p22 + b22[0];
    float m2 = fmaxf(u0, u1);
    float r0 = expf(u0 - m2), r1 = expf(u1 - m2);
    float inv2 = 1.0f / (r0 + r1);
    float t0 = r0 * inv2, t1 = r1 * inv2;
    t_im[(size_t)node * DD + lane]      = t0 * a0 + t1 * c0;
    t_im[(size_t)node * DD + lane + 32] = t0 * a1 + t1 * c1;
}

// ---------------- C = A[N,64] @ B[64,64] (+bias) (+add), blockIdx.y selects B/C slice --------
__global__ void gemm64(const float* __restrict__ A,
                       const float* __restrict__ B0, size_t bstride,
                       const float* __restrict__ bias, const float* __restrict__ add,
                       float* __restrict__ C0, size_t cstride, int nrows) {
    const float* B = B0 + (size_t)blockIdx.y * bstride;
    float* C       = C0 + (size_t)blockIdx.y * cstride;
    __shared__ float As[64][65];
    __shared__ float Bs[64][65];
    int row0 = blockIdx.x * 64;
    int tid  = threadIdx.x;
    for (int i = tid; i < 4096; i += 256) Bs[i >> 6][i & 63] = B[i];
    for (int i = tid; i < 4096; i += 256) {
        int rr = i >> 6, cc = i & 63;
        int gr = row0 + rr;
        As[rr][cc] = (gr < nrows) ? A[(size_t)gr * 64 + cc] : 0.0f;
    }
    __syncthreads();
    int tx = tid & 15, ty = tid >> 4;
    float acc[4][4];
    #pragma unroll
    for (int i = 0; i < 4; i++)
        #pragma unroll
        for (int j = 0; j < 4; j++) acc[i][j] = 0.0f;
    #pragma unroll 8
    for (int k = 0; k < 64; k++) {
        float a[4], b[4];
        #pragma unroll
        for (int i = 0; i < 4; i++) a[i] = As[ty * 4 + i][k];
        #pragma unroll
        for (int j = 0; j < 4; j++) b[j] = Bs[k][tx * 4 + j];
        #pragma unroll
        for (int i = 0; i < 4; i++)
            #pragma unroll
            for (int j = 0; j < 4; j++) acc[i][j] += a[i] * b[j];
    }
    #pragma unroll
    for (int i = 0; i < 4; i++) {
        int gr = row0 + ty * 4 + i;
        if (gr >= nrows) continue;
        #pragma unroll
        for (int j = 0; j < 4; j++) {
            int c = tx * 4 + j;
            float v = acc[i][j];
            if (bias) v += bias[c];
            if (add)  v += add[(size_t)gr * 64 + c];
            C[(size_t)gr * 64 + c] = v;
        }
    }
}

// ---------------- hidden = leaky_relu([ex|im][N,128] @ W1[128,64] + b1) ----------------
__global__ void mlp1_kernel(const float* __restrict__ ex, const float* __restrict__ im,
                            const float* __restrict__ W1, const float* __restrict__ b1,
                            float* __restrict__ hidden, int nrows) {
    __shared__ float As[64][65];
    __shared__ float Bs[64][65];
    int row0 = blockIdx.x * 64;
    int tid  = threadIdx.x;
    int tx = tid & 15, ty = tid >> 4;
    float acc[4][4];
    #pragma unroll
    for (int i = 0; i < 4; i++)
        #pragma unroll
        for (int j = 0; j < 4; j++) acc[i][j] = 0.0f;
    for (int kb = 0; kb < 2; kb++) {
        const float* Asrc = kb ? im : ex;
        for (int i = tid; i < 4096; i += 256) {
            int rr = i >> 6, cc = i & 63;
            int gr = row0 + rr;
            As[rr][cc] = (gr < nrows) ? Asrc[(size_t)gr * 64 + cc] : 0.0f;
        }
        for (int i = tid; i < 4096; i += 256) {
            int kk = i >> 6, cc = i & 63;
            Bs[kk][cc] = W1[(size_t)(kb * 64 + kk) * 64 + cc];
        }
        __syncthreads();
        #pragma unroll 8
        for (int k = 0; k < 64; k++) {
            float a[4], b[4];
            #pragma unroll
            for (int i = 0; i < 4; i++) a[i] = As[ty * 4 + i][k];
            #pragma unroll
            for (int j = 0; j < 4; j++) b[j] = Bs[k][tx * 4 + j];
            #pragma unroll
            for (int i = 0; i < 4; i++)
                #pragma unroll
                for (int j = 0; j < 4; j++) acc[i][j] += a[i] * b[j];
        }
        __syncthreads();
    }
    #pragma unroll
    for (int i = 0; i < 4; i++) {
        int gr = row0 + ty * 4 + i;
        if (gr >= nrows) continue;
        #pragma unroll
        for (int j = 0; j < 4; j++) {
            int c = tx * 4 + j;
            float v = acc[i][j] + b1[c];
            v = (v > 0.0f) ? v : 0.01f * v;
            hidden[(size_t)gr * 64 + c] = v;
        }
    }
}

// ---------------- host ----------------
extern "C" void kernel_launch(void* const* d_in, const int* in_sizes, int n_in,
                              void* d_out, int out_size) {
    (void)in_sizes; (void)n_in; (void)out_size;
    const int*   ei_ex   = (const int*)d_in[0];
    const int*   et_ex   = (const int*)d_in[1];
    const int*   ei_im   = (const int*)d_in[2];
    const int*   et_im   = (const int*)d_in[3];
    const float* W1_ex   = (const float*)d_in[4];
    const float* root1_ex= (const float*)d_in[5];
    const float* b1_ex   = (const float*)d_in[6];
    const float* W1_im   = (const float*)d_in[7];
    const float* root1_im= (const float*)d_in[8];
    const float* b1_im   = (const float*)d_in[9];
    const float* W2_ex   = (const float*)d_in[10];
    const float* root2_ex= (const float*)d_in[11];
    const float* b2_ex   = (const float*)d_in[12];
    const float* W2_im   = (const float*)d_in[13];
    const float* root2_im= (const float*)d_in[14];
    const float* b2_im   = (const float*)d_in[15];
    const float* aw11 = (const float*)d_in[16]; const float* ab11 = (const float*)d_in[17];
    const float* aw12 = (const float*)d_in[18]; const float* ab12 = (const float*)d_in[19];
    const float* aw21 = (const float*)d_in[20]; const float* ab21 = (const float*)d_in[21];
    const float* aw22 = (const float*)d_in[22]; const float* ab22 = (const float*)d_in[23];
    const float* agg_W1 = (const float*)d_in[24]; const float* agg_b1 = (const float*)d_in[25];
    const float* agg_W2 = (const float*)d_in[26]; const float* agg_b2 = (const float*)d_in[27];
    float* out = (float*)d_out;

    const int* src_ex = ei_ex;
    const int* dst_ex = ei_ex + EEX;
    const int* src_im = ei_im;
    const int* dst_im = ei_im + EIM;

    // symbol addresses
    void *p_cnt_ex, *p_cnt_im, *p_inv_ex, *p_inv_im, *p_ex_x1, *p_im_x1,
         *p_t_ex, *p_t_im, *p_ex_sum, *p_im_sum, *p_hidden, *p_z_ex, *p_z_im;
    cudaGetSymbolAddress(&p_cnt_ex, g_cnt_ex);
    cudaGetSymbolAddress(&p_cnt_im, g_cnt_im);
    cudaGetSymbolAddress(&p_inv_ex, g_inv_ex);
    cudaGetSymbolAddress(&p_inv_im, g_inv_im);
    cudaGetSymbolAddress(&p_ex_x1, g_ex_x1);
    cudaGetSymbolAddress(&p_im_x1, g_im_x1);
    cudaGetSymbolAddress(&p_t_ex, g_t_ex);
    cudaGetSymbolAddress(&p_t_im, g_t_im);
    cudaGetSymbolAddress(&p_ex_sum, g_ex_sum);
    cudaGetSymbolAddress(&p_im_sum, g_im_sum);
    cudaGetSymbolAddress(&p_hidden, g_hidden);
    cudaGetSymbolAddress(&p_z_ex, g_z_ex);
    cudaGetSymbolAddress(&p_z_im, g_z_im);

    float* cnt_ex_f = (float*)p_cnt_ex;  // int storage, memset as bytes
    float* zex  = (float*)p_z_ex;
    float* zim  = (float*)p_z_im;

    // 1) zero counts
    cudaMemsetAsync(p_cnt_ex, 0, sizeof(int) * NN * REX);
    cudaMemsetAsync(p_cnt_im, 0, sizeof(int) * NN * RIM);
    (void)cnt_ex_f;

    // 2) counts
    count_kernel<<<(EEX + 255) / 256, 256>>>(dst_ex, et_ex, EEX, (int*)p_cnt_ex, REX);
    count_kernel<<<(EIM + 255) / 256, 256>>>(dst_im, et_im, EIM, (int*)p_cnt_im, RIM);

    // 3) inverse counts
    make_inv<<<(NN * REX + 255) / 256, 256>>>((const int*)p_cnt_ex, (float*)p_inv_ex, NN * REX);
    make_inv<<<(NN * RIM + 255) / 256, 256>>>((const int*)p_cnt_im, (float*)p_inv_im, NN * RIM);

    // 4) x1 init: root + bias
    init_x1<<<(NN * DD + 255) / 256, 256>>>(root1_ex, b1_ex, (float*)p_ex_x1, NN * DD);
    init_x1<<<(NN * DD + 255) / 256, 256>>>(root1_im, b1_im, (float*)p_im_x1, NN * DD);

    // 5) layer-1 scatter (embedding gather + scaled red)
    scatter_kernel<<<(EEX * 16) / 256, 256>>>(W1_ex, src_ex, dst_ex, et_ex,
                                              (const float*)p_inv_ex, REX, (float*)p_ex_x1, EEX);
    scatter_kernel<<<(EIM * 16) / 256, 256>>>(W1_im, src_im, dst_im, et_im,
                                              (const float*)p_inv_im, RIM, (float*)p_im_x1, EIM);

    // 6) ATTITU fusion
    attitu_kernel<<<(NN * 32 + 255) / 256, 256>>>((const float*)p_ex_x1, (const float*)p_im_x1,
                                                  aw11, ab11, aw12, ab12, aw21, ab21, aw22, ab22,
                                                  (float*)p_t_ex, (float*)p_t_im, NN);

    const int tiles = (NN + 63) / 64;

    // 7) base: ex_sum = ex_x1 + t_ex @ root2 + b2 ; same for im
    gemm64<<<dim3(tiles, 1), 256>>>((const float*)p_t_ex, root2_ex, 0, b2_ex,
                                    (const float*)p_ex_x1, (float*)p_ex_sum, 0, NN);
    gemm64<<<dim3(tiles, 1), 256>>>((const float*)p_t_im, root2_im, 0, b2_im,
                                    (const float*)p_im_x1, (float*)p_im_sum, 0, NN);

    // 8) z[r] = t @ W2[r]
    gemm64<<<dim3(tiles, REX), 256>>>((const float*)p_t_ex, W2_ex, (size_t)DD * DD,
                                      nullptr, nullptr, zex, (size_t)NN * DD, NN);
    gemm64<<<dim3(tiles, RIM), 256>>>((const float*)p_t_im, W2_im, (size_t)DD * DD,
                                      nullptr, nullptr, zim, (size_t)NN * DD, NN);

    // 9) layer-2 scatter (z gather + scaled red into ex_sum/im_sum)
    scatter_kernel<<<(EEX * 16) / 256, 256>>>(zex, src_ex, dst_ex, et_ex,
                                              (const float*)p_inv_ex, REX, (float*)p_ex_sum, EEX);
    scatter_kernel<<<(EIM * 16) / 256, 256>>>(zim, src_im, dst_im, et_im,
                                              (const float*)p_inv_im, RIM, (float*)p_im_sum, EIM);

    // 10) final MLP
    mlp1_kernel<<<tiles, 256>>>((const float*)p_ex_sum, (const float*)p_im_sum,
                                agg_W1, agg_b1, (float*)p_hidden, NN);
    gemm64<<<dim3(tiles, 1), 256>>>((const float*)p_hidden, agg_W2, 0, agg_b2,
                                    nullptr, out, 0, NN);
}

// round 3
// speedup vs baseline: 1.4288x; 1.4288x over previous
#include <cuda_runtime.h>
#include <cstddef>

#define NN  100000
#define DD  64
#define REX 8
#define RIM 4
#define EEX 2000000
#define EIM 1000000

// ---------------- scratch (static device globals; no allocation) ----------------
__device__ int   g_cnt_ex[NN * REX];
__device__ int   g_cnt_im[NN * RIM];
__device__ int   g_offs_ex[NN * REX];
__device__ int   g_offs_im[NN * RIM];
__device__ int   g_cur_ex[NN * REX];
__device__ int   g_cur_im[NN * RIM];
__device__ int   g_bs_ex[1024];
__device__ int   g_bs_im[1024];
__device__ int   g_bs2_ex[1024];
__device__ int   g_bs2_im[1024];
__device__ int   g_ssrc_ex[EEX];
__device__ int   g_ssrc_im[EIM];
__device__ float g_ex_x1[NN * DD];
__device__ float g_im_x1[NN * DD];
__device__ float g_t_ex[NN * DD];
__device__ float g_t_im[NN * DD];
__device__ float g_ex_sum[NN * DD];
__device__ float g_im_sum[NN * DD];
__device__ float g_hidden[NN * DD];
__device__ float g_h_ex[(size_t)NN * REX * DD];   // 204.8 MB
__device__ float g_h_im[(size_t)NN * RIM * DD];   // 102.4 MB

// ---------------- count per (dst, relation) ----------------
__global__ void count_kernel(const int* __restrict__ dst, const int* __restrict__ typ,
                             int E, int* __restrict__ cnt, int R) {
    int e = blockIdx.x * blockDim.x + threadIdx.x;
    if (e >= E) return;
    atomicAdd(&cnt[dst[e] * R + typ[e]], 1);
}

// ---------------- exclusive scan, 256 threads/block, 1024 elems/block ----------------
__global__ void scan1(const int* __restrict__ in, int n, int* __restrict__ out,
                      int* __restrict__ bsum) {
    __shared__ int s[256];
    int t = threadIdx.x;
    int base = blockIdx.x * 1024 + t * 4;
    int v0 = (base     < n) ? in[base]     : 0;
    int v1 = (base + 1 < n) ? in[base + 1] : 0;
    int v2 = (base + 2 < n) ? in[base + 2] : 0;
    int v3 = (base + 3 < n) ? in[base + 3] : 0;
    int tot = v0 + v1 + v2 + v3;
    s[t] = tot;
    __syncthreads();
    #pragma unroll
    for (int o = 1; o < 256; o <<= 1) {
        int x = (t >= o) ? s[t - o] : 0;
        __syncthreads();
        s[t] += x;
        __syncthreads();
    }
    int excl = s[t] - tot;
    if (base     < n) out[base]     = excl;
    if (base + 1 < n) out[base + 1] = excl + v0;
    if (base + 2 < n) out[base + 2] = excl + v0 + v1;
    if (base + 3 < n) out[base + 3] = excl + v0 + v1 + v2;
    if (t == 255 && bsum) bsum[blockIdx.x] = s[255];
}

__global__ void scan_add4(int* __restrict__ out, const int* __restrict__ boff, int n) {
    int base = blockIdx.x * 1024 + threadIdx.x * 4;
    int a = boff[blockIdx.x];
    if (base     < n) out[base]     += a;
    if (base + 1 < n) out[base + 1] += a;
    if (base + 2 < n) out[base + 2] += a;
    if (base + 3 < n) out[base + 3] += a;
}

// ---------------- counting-sort scatter: group edges by (dst, r) ----------------
__global__ void sort_kernel(const int* __restrict__ src, const int* __restrict__ dst,
                            const int* __restrict__ typ, int E, int R,
                            int* __restrict__ cursor, int* __restrict__ ssrc) {
    int e = blockIdx.x * blockDim.x + threadIdx.x;
    if (e >= E) return;
    int key = dst[e] * R + typ[e];
    int pos = atomicAdd(&cursor[key], 1);
    ssrc[pos] = src[e];
}

// ---------------- layer-1 aggregate: owner-write, no atomics ----------------
// 16 lanes per dst node. out[d] = root[d] + bias + sum_r mean_e W[r, ssrc[e]]
__global__ void agg_l1(const float* __restrict__ W, const int* __restrict__ ssrc,
                       const int* __restrict__ offs, const float* __restrict__ root,
                       const float* __restrict__ bias, float* __restrict__ out,
                       int R, int E) {
    int idx  = blockIdx.x * blockDim.x + threadIdx.x;
    int d    = idx >> 4;
    int lane = idx & 15;
    if (d >= NN) return;
    float4 b = reinterpret_cast<const float4*>(bias)[lane];
    float4 acc = reinterpret_cast<const float4*>(root)[(size_t)d * 16 + lane];
    acc.x += b.x; acc.y += b.y; acc.z += b.z; acc.w += b.w;
    int beg = offs[d * R];
    for (int r = 0; r < R; r++) {
        int key = d * R + r;
        int end = (key + 1 < NN * R) ? offs[key + 1] : E;
        if (end > beg) {
            float4 s = make_float4(0.f, 0.f, 0.f, 0.f);
            for (int e = beg; e < end; e++) {
                int sv = ssrc[e];
                float4 v = reinterpret_cast<const float4*>(W)[((size_t)r * NN + sv) * 16 + lane];
                s.x += v.x; s.y += v.y; s.z += v.z; s.w += v.w;
            }
            float inv = 1.0f / (float)(end - beg);
            acc.x += s.x * inv; acc.y += s.y * inv; acc.z += s.z * inv; acc.w += s.w * inv;
        }
        beg = end;
    }
    reinterpret_cast<float4*>(out)[(size_t)d * 16 + lane] = acc;
}

// ---------------- layer-2 mean aggregate: h[(d*R+r)] = mean_e t[ssrc[e]] ----------------
__global__ void agg_h(const float* __restrict__ t, const int* __restrict__ ssrc,
                      const int* __restrict__ offs, float* __restrict__ h,
                      int R, int E) {
    int idx  = blockIdx.x * blockDim.x + threadIdx.x;
    int pair = idx >> 4;
    int lane = idx & 15;
    if (pair >= NN * R) return;
    int beg = offs[pair];
    int end = (pair + 1 < NN * R) ? offs[pair + 1] : E;
    float4 s = make_float4(0.f, 0.f, 0.f, 0.f);
    for (int e = beg; e < end; e++) {
        int sv = ssrc[e];
        float4 v = reinterpret_cast<const float4*>(t)[(size_t)sv * 16 + lane];
        s.x += v.x; s.y += v.y; s.z += v.z; s.w += v.w;
    }
    if (end > beg) {
        float inv = 1.0f / (float)(end - beg);
        s.x *= inv; s.y *= inv; s.z *= inv; s.w *= inv;
    }
    reinterpret_cast<float4*>(h)[(size_t)pair * 16 + lane] = s;
}

// ---------------- ATTITU fusion (warp per node) ----------------
__global__ void attitu_kernel(const float* __restrict__ ex1, const float* __restrict__ im1,
                              const float* __restrict__ w11, const float* __restrict__ b11,
                              const float* __restrict__ w12, const float* __restrict__ b12,
                              const float* __restrict__ w21, const float* __restrict__ b21,
                              const float* __restrict__ w22, const float* __restrict__ b22,
                              float* __restrict__ t_ex, float* __restrict__ t_im, int nnodes) {
    int g    = blockIdx.x * blockDim.x + threadIdx.x;
    int node = g >> 5;
    int lane = g & 31;
    if (node >= nnodes) return;
    const float* e1 = ex1 + (size_t)node * DD;
    const float* e2 = im1 + (size_t)node * DD;
    float a0 = e1[lane], a1 = e1[lane + 32];
    float c0 = e2[lane], c1 = e2[lane + 32];
    float p11 = a0 * w11[lane] + a1 * w11[lane + 32];
    float p12 = c0 * w12[lane] + c1 * w12[lane + 32];
    float p21 = a0 * w21[lane] + a1 * w21[lane + 32];
    float p22 = c0 * w22[lane] + c1 * w22[lane + 32];
    #pragma unroll
    for (int o = 16; o > 0; o >>= 1) {
        p11 += __shfl_xor_sync(0xFFFFFFFF, p11, o);
        p12 += __shfl_xor_sync(0xFFFFFFFF, p12, o);
        p21 += __shfl_xor_sync(0xFFFFFFFF, p21, o);
        p22 += __shfl_xor_sync(0xFFFFFFFF, p22, o);
    }
    float l0 = p11 + b11[0], l1 = p12 + b12[0];
    float m = fmaxf(l0, l1);
    float q0 = expf(l0 - m), q1 = expf(l1 - m);
    float inv = 1.0f / (q0 + q1);
    float s0 = q0 * inv, s1 = q1 * inv;
    t_ex[(size_t)node * DD + lane]      = s0 * a0 + s1 * c0;
    t_ex[(size_t)node * DD + lane + 32] = s0 * a1 + s1 * c1;
    float u0 = p21 + b21[0], u1 = p22 + b22[0];
    float m2 = fmaxf(u0, u1);
    float r0 = expf(u0 - m2), r1 = expf(u1 - m2);
    float inv2 = 1.0f / (r0 + r1);
    float t0 = r0 * inv2, t1 = r1 * inv2;
    t_im[(size_t)node * DD + lane]      = t0 * a0 + t1 * c0;
    t_im[(size_t)node * DD + lane + 32] = t0 * a1 + t1 * c1;
}

// ---------------- unified GEMM: C[N,64] = epi( sum_kb A(kb)[N,64] @ B(kb)[64,64] ) ------
// kb < kbn0: A = A0 + kb*64 (row-stride stride0), B = B0 + kb*4096
// kb >= kbn0: A = A1 + (kb-kbn0)*64 (row-stride stride1), B = B1 + (kb-kbn0)*4096
// epi: +bias (opt), +add (opt), leaky-relu (opt)
// 128x64 tile, 256 threads, 8x4 per-thread accumulators.
__global__ void gemm_uni(const float* __restrict__ A0, int stride0, int kbn0,
                         const float* __restrict__ A1, int stride1, int kbn,
                         const float* __restrict__ B0, const float* __restrict__ B1,
                         const float* __restrict__ bias, const float* __restrict__ add,
                         int leaky, float* __restrict__ C, int nrows) {
    __shared__ float As[128][64];
    __shared__ float Bs[64][64];
    int row0 = blockIdx.x * 128;
    int tid  = threadIdx.x;
    int tx = tid & 15, ty = tid >> 4;
    float acc[8][4];
    #pragma unroll
    for (int i = 0; i < 8; i++)
        #pragma unroll
        for (int j = 0; j < 4; j++) acc[i][j] = 0.0f;

    for (int kb = 0; kb < kbn; kb++) {
        const float* A; int astr; const float* B;
        if (kb < kbn0) { A = A0 + kb * 64;          astr = stride0; B = B0 + (size_t)kb * 4096; }
        else           { A = A1 + (kb - kbn0) * 64; astr = stride1; B = B1 + (size_t)(kb - kbn0) * 4096; }
        // load As (128x64 floats) as float4: 2048 float4s, 8 per thread
        #pragma unroll
        for (int i = 0; i < 8; i++) {
            int f = tid + i * 256;           // float4 index
            int rr = f >> 4, c4 = f & 15;
            int gr = row0 + rr;
            float4 v = make_float4(0.f, 0.f, 0.f, 0.f);
            if (gr < nrows)
                v = *reinterpret_cast<const float4*>(A + (size_t)gr * astr + c4 * 4);
            *reinterpret_cast<float4*>(&As[rr][c4 * 4]) = v;
        }
        // load Bs (64x64): 1024 float4s, 4 per thread
        #pragma unroll
        for (int i = 0; i < 4; i++) {
            int f = tid + i * 256;
            int rr = f >> 4, c4 = f & 15;
            float4 v = *reinterpret_cast<const float4*>(B + rr * 64 + c4 * 4);
            *reinterpret_cast<float4*>(&Bs[rr][c4 * 4]) = v;
        }
        __syncthreads();
        #pragma unroll 4
        for (int k = 0; k < 64; k++) {
            float b0 = Bs[k][tx * 4 + 0];
            float b1 = Bs[k][tx * 4 + 1];
            float b2 = Bs[k][tx * 4 + 2];
            float b3 = Bs[k][tx * 4 + 3];
            #pragma unroll
            for (int i = 0; i < 8; i++) {
                float a = As[ty * 8 + i][k];
                acc[i][0] += a * b0;
                acc[i][1] += a * b1;
                acc[i][2] += a * b2;
                acc[i][3] += a * b3;
            }
        }
        __syncthreads();
    }
    #pragma unroll
    for (int i = 0; i < 8; i++) {
        int gr = row0 + ty * 8 + i;
        if (gr >= nrows) continue;
        #pragma unroll
        for (int j = 0; j < 4; j++) {
            int c = tx * 4 + j;
            float v = acc[i][j];
            if (bias) v += bias[c];
            if (add)  v += add[(size_t)gr * 64 + c];
            if (leaky) v = (v > 0.0f) ? v : 0.01f * v;
            C[(size_t)gr * 64 + c] = v;
        }
    }
}

// ---------------- host ----------------
extern "C" void kernel_launch(void* const* d_in, const int* in_sizes, int n_in,
                              void* d_out, int out_size) {
    (void)in_sizes; (void)n_in; (void)out_size;
    const int*   ei_ex   = (const int*)d_in[0];
    const int*   et_ex   = (const int*)d_in[1];
    const int*   ei_im   = (const int*)d_in[2];
    const int*   et_im   = (const int*)d_in[3];
    const float* W1_ex   = (const float*)d_in[4];
    const float* root1_ex= (const float*)d_in[5];
    const float* b1_ex   = (const float*)d_in[6];
    const float* W1_im   = (const float*)d_in[7];
    const float* root1_im= (const float*)d_in[8];
    const float* b1_im   = (const float*)d_in[9];
    const float* W2_ex   = (const float*)d_in[10];
    const float* root2_ex= (const float*)d_in[11];
    const float* b2_ex   = (const float*)d_in[12];
    const float* W2_im   = (const float*)d_in[13];
    const float* root2_im= (const float*)d_in[14];
    const float* b2_im   = (const float*)d_in[15];
    const float* aw11 = (const float*)d_in[16]; const float* ab11 = (const float*)d_in[17];
    const float* aw12 = (const float*)d_in[18]; const float* ab12 = (const float*)d_in[19];
    const float* aw21 = (const float*)d_in[20]; const float* ab21 = (const float*)d_in[21];
    const float* aw22 = (const float*)d_in[22]; const float* ab22 = (const float*)d_in[23];
    const float* agg_W1 = (const float*)d_in[24]; const float* agg_b1 = (const float*)d_in[25];
    const float* agg_W2 = (const float*)d_in[26]; const float* agg_b2 = (const float*)d_in[27];
    float* out = (float*)d_out;

    const int* src_ex = ei_ex;
    const int* dst_ex = ei_ex + EEX;
    const int* src_im = ei_im;
    const int* dst_im = ei_im + EIM;

    void *p_cnt_ex, *p_cnt_im, *p_offs_ex, *p_offs_im, *p_cur_ex, *p_cur_im,
         *p_bs_ex, *p_bs_im, *p_bs2_ex, *p_bs2_im, *p_ssrc_ex, *p_ssrc_im,
         *p_ex_x1, *p_im_x1, *p_t_ex, *p_t_im, *p_ex_sum, *p_im_sum,
         *p_hidden, *p_h_ex, *p_h_im;
    cudaGetSymbolAddress(&p_cnt_ex, g_cnt_ex);
    cudaGetSymbolAddress(&p_cnt_im, g_cnt_im);
    cudaGetSymbolAddress(&p_offs_ex, g_offs_ex);
    cudaGetSymbolAddress(&p_offs_im, g_offs_im);
    cudaGetSymbolAddress(&p_cur_ex, g_cur_ex);
    cudaGetSymbolAddress(&p_cur_im, g_cur_im);
    cudaGetSymbolAddress(&p_bs_ex, g_bs_ex);
    cudaGetSymbolAddress(&p_bs_im, g_bs_im);
    cudaGetSymbolAddress(&p_bs2_ex, g_bs2_ex);
    cudaGetSymbolAddress(&p_bs2_im, g_bs2_im);
    cudaGetSymbolAddress(&p_ssrc_ex, g_ssrc_ex);
    cudaGetSymbolAddress(&p_ssrc_im, g_ssrc_im);
    cudaGetSymbolAddress(&p_ex_x1, g_ex_x1);
    cudaGetSymbolAddress(&p_im_x1, g_im_x1);
    cudaGetSymbolAddress(&p_t_ex, g_t_ex);
    cudaGetSymbolAddress(&p_t_im, g_t_im);
    cudaGetSymbolAddress(&p_ex_sum, g_ex_sum);
    cudaGetSymbolAddress(&p_im_sum, g_im_sum);
    cudaGetSymbolAddress(&p_hidden, g_hidden);
    cudaGetSymbolAddress(&p_h_ex, g_h_ex);
    cudaGetSymbolAddress(&p_h_im, g_h_im);

    const int NRE = NN * REX;                 // 800000
    const int NRI = NN * RIM;                 // 400000
    const int NBE = (NRE + 1023) / 1024;      // 782
    const int NBI = (NRI + 1023) / 1024;      // 391

    // 1) counts
    cudaMemsetAsync(p_cnt_ex, 0, sizeof(int) * NRE);
    cudaMemsetAsync(p_cnt_im, 0, sizeof(int) * NRI);
    count_kernel<<<(EEX + 255) / 256, 256>>>(dst_ex, et_ex, EEX, (int*)p_cnt_ex, REX);
    count_kernel<<<(EIM + 255) / 256, 256>>>(dst_im, et_im, EIM, (int*)p_cnt_im, RIM);

    // 2) exclusive scan -> segment offsets (3 phases, 256-thread blocks, no aliasing)
    scan1<<<NBE, 256>>>((const int*)p_cnt_ex, NRE, (int*)p_offs_ex, (int*)p_bs_ex);
    scan1<<<NBI, 256>>>((const int*)p_cnt_im, NRI, (int*)p_offs_im, (int*)p_bs_im);
    scan1<<<1, 256>>>((const int*)p_bs_ex, NBE, (int*)p_bs2_ex, nullptr);
    scan1<<<1, 256>>>((const int*)p_bs_im, NBI, (int*)p_bs2_im, nullptr);
    scan_add4<<<NBE, 256>>>((int*)p_offs_ex, (const int*)p_bs2_ex, NRE);
    scan_add4<<<NBI, 256>>>((int*)p_offs_im, (const int*)p_bs2_im, NRI);

    // 3) counting sort: group src by (dst, r)
    cudaMemcpyAsync(p_cur_ex, p_offs_ex, sizeof(int) * NRE, cudaMemcpyDeviceToDevice);
    cudaMemcpyAsync(p_cur_im, p_offs_im, sizeof(int) * NRI, cudaMemcpyDeviceToDevice);
    sort_kernel<<<(EEX + 255) / 256, 256>>>(src_ex, dst_ex, et_ex, EEX, REX,
                                            (int*)p_cur_ex, (int*)p_ssrc_ex);
    sort_kernel<<<(EIM + 255) / 256, 256>>>(src_im, dst_im, et_im, EIM, RIM,
                                            (int*)p_cur_im, (int*)p_ssrc_im);

    // 4) layer-1 (owner-write aggregation)
    agg_l1<<<(NN * 16 + 255) / 256, 256>>>(W1_ex, (const int*)p_ssrc_ex, (const int*)p_offs_ex,
                                           root1_ex, b1_ex, (float*)p_ex_x1, REX, EEX);
    agg_l1<<<(NN * 16 + 255) / 256, 256>>>(W1_im, (const int*)p_ssrc_im, (const int*)p_offs_im,
                                           root1_im, b1_im, (float*)p_im_x1, RIM, EIM);

    // 5) ATTITU fusion
    attitu_kernel<<<(NN * 32 + 255) / 256, 256>>>((const float*)p_ex_x1, (const float*)p_im_x1,
                                                  aw11, ab11, aw12, ab12, aw21, ab21, aw22, ab22,
                                                  (float*)p_t_ex, (float*)p_t_im, NN);

    // 6) layer-2 per-(dst,r) means from L2-resident t
    agg_h<<<(NRE * 16 + 255) / 256, 256>>>((const float*)p_t_ex, (const int*)p_ssrc_ex,
                                           (const int*)p_offs_ex, (float*)p_h_ex, REX, EEX);
    agg_h<<<(NRI * 16 + 255) / 256, 256>>>((const float*)p_t_im, (const int*)p_ssrc_im,
                                           (const int*)p_offs_im, (float*)p_h_im, RIM, EIM);

    const int tiles = (NN + 127) / 128;   // 782

    // 7) fused: ex_sum = ex_x1 + t_ex@root2_ex + b2_ex + h_ex@W2_ex   (kbn = 1 + R)
    gemm_uni<<<tiles, 256>>>((const float*)p_t_ex, 64, 1,
                             (const float*)p_h_ex, REX * 64, 1 + REX,
                             root2_ex, W2_ex, b2_ex, (const float*)p_ex_x1,
                             0, (float*)p_ex_sum, NN);
    gemm_uni<<<tiles, 256>>>((const float*)p_t_im, 64, 1,
                             (const float*)p_h_im, RIM * 64, 1 + RIM,
                             root2_im, W2_im, b2_im, (const float*)p_im_x1,
                             0, (float*)p_im_sum, NN);

    // 8) hidden = leaky_relu([ex_sum | im_sum] @ agg_W1 + agg_b1)
    gemm_uni<<<tiles, 256>>>((const float*)p_ex_sum, 64, 1,
                             (const float*)p_im_sum, 64, 2,
                             agg_W1, agg_W1 + 64 * 64, agg_b1, nullptr,
                             1, (float*)p_hidden, NN);

    // 9) out = hidden @ agg_W2 + agg_b2
    gemm_uni<<<tiles, 256>>>((const float*)p_hidden, 64, 1,
                             nullptr, 0, 1,
                             agg_W2, nullptr, agg_b2, nullptr,
                             0, out, NN);
}

// round 4
// speedup vs baseline: 1.5820x; 1.1072x over previous
#include <cuda_runtime.h>
#include <cstddef>

#define NN  100000
#define DD  64
#define REX 8
#define RIM 4
#define EEX 2000000
#define EIM 1000000

// ---------------- scratch (static device globals; no allocation) ----------------
__device__ int   g_cnt_ex[NN * REX];
__device__ int   g_cnt_im[NN * RIM];
__device__ int   g_offs_ex[NN * REX];
__device__ int   g_offs_im[NN * RIM];
__device__ int   g_cur_ex[NN * REX];
__device__ int   g_cur_im[NN * RIM];
__device__ int   g_bs_ex[1024];
__device__ int   g_bs_im[1024];
__device__ int   g_bs2_ex[1024];
__device__ int   g_bs2_im[1024];
__device__ int   g_ssrc_ex[EEX];
__device__ int   g_ssrc_im[EIM];
__device__ float g_ex_x1[NN * DD];
__device__ float g_im_x1[NN * DD];
__device__ float g_t_ex[NN * DD];
__device__ float g_t_im[NN * DD];
__device__ float g_ex_sum[NN * DD];
__device__ float g_im_sum[NN * DD];
__device__ float g_hidden[NN * DD];

// ---------------- count per (dst, relation) ----------------
__global__ void count_kernel(const int* __restrict__ dst, const int* __restrict__ typ,
                             int E, int* __restrict__ cnt, int R) {
    int e = blockIdx.x * blockDim.x + threadIdx.x;
    if (e >= E) return;
    atomicAdd(&cnt[dst[e] * R + typ[e]], 1);
}

// ---------------- exclusive scan, 256 threads/block, 1024 elems/block ----------------
__global__ void scan1(const int* __restrict__ in, int n, int* __restrict__ out,
                      int* __restrict__ bsum) {
    __shared__ int s[256];
    int t = threadIdx.x;
    int base = blockIdx.x * 1024 + t * 4;
    int v0 = (base     < n) ? in[base]     : 0;
    int v1 = (base + 1 < n) ? in[base + 1] : 0;
    int v2 = (base + 2 < n) ? in[base + 2] : 0;
    int v3 = (base + 3 < n) ? in[base + 3] : 0;
    int tot = v0 + v1 + v2 + v3;
    s[t] = tot;
    __syncthreads();
    #pragma unroll
    for (int o = 1; o < 256; o <<= 1) {
        int x = (t >= o) ? s[t - o] : 0;
        __syncthreads();
        s[t] += x;
        __syncthreads();
    }
    int excl = s[t] - tot;
    if (base     < n) out[base]     = excl;
    if (base + 1 < n) out[base + 1] = excl + v0;
    if (base + 2 < n) out[base + 2] = excl + v0 + v1;
    if (base + 3 < n) out[base + 3] = excl + v0 + v1 + v2;
    if (t == 255 && bsum) bsum[blockIdx.x] = s[255];
}

__global__ void scan_add4(int* __restrict__ out, const int* __restrict__ boff, int n) {
    int base = blockIdx.x * 1024 + threadIdx.x * 4;
    int a = boff[blockIdx.x];
    if (base     < n) out[base]     += a;
    if (base + 1 < n) out[base + 1] += a;
    if (base + 2 < n) out[base + 2] += a;
    if (base + 3 < n) out[base + 3] += a;
}

// ---------------- counting-sort scatter: group edges by (dst, r) ----------------
__global__ void sort_kernel(const int* __restrict__ src, const int* __restrict__ dst,
                            const int* __restrict__ typ, int E, int R,
                            int* __restrict__ cursor, int* __restrict__ ssrc) {
    int e = blockIdx.x * blockDim.x + threadIdx.x;
    if (e >= E) return;
    int key = dst[e] * R + typ[e];
    int pos = atomicAdd(&cursor[key], 1);
    ssrc[pos] = src[e];
}

// ---------------- layer-1 aggregate: owner-write, no atomics ----------------
// 16 lanes per dst node. out[d] = root[d] + bias + sum_r mean_e W[r, ssrc[e]]
__global__ void agg_l1(const float* __restrict__ W, const int* __restrict__ ssrc,
                       const int* __restrict__ offs, const float* __restrict__ root,
                       const float* __restrict__ bias, float* __restrict__ out,
                       int R, int E) {
    int idx  = blockIdx.x * blockDim.x + threadIdx.x;
    int d    = idx >> 4;
    int lane = idx & 15;
    if (d >= NN) return;
    float4 b = reinterpret_cast<const float4*>(bias)[lane];
    float4 acc = reinterpret_cast<const float4*>(root)[(size_t)d * 16 + lane];
    acc.x += b.x; acc.y += b.y; acc.z += b.z; acc.w += b.w;
    int beg = offs[d * R];
    for (int r = 0; r < R; r++) {
        int key = d * R + r;
        int end = (key + 1 < NN * R) ? offs[key + 1] : E;
        if (end > beg) {
            float4 s = make_float4(0.f, 0.f, 0.f, 0.f);
            for (int e = beg; e < end; e++) {
                int sv = ssrc[e];
                float4 v = reinterpret_cast<const float4*>(W)[((size_t)r * NN + sv) * 16 + lane];
                s.x += v.x; s.y += v.y; s.z += v.z; s.w += v.w;
            }
            float inv = 1.0f / (float)(end - beg);
            acc.x += s.x * inv; acc.y += s.y * inv; acc.z += s.z * inv; acc.w += s.w * inv;
        }
        beg = end;
    }
    reinterpret_cast<float4*>(out)[(size_t)d * 16 + lane] = acc;
}

// ---------------- ATTITU fusion (warp per node) ----------------
__global__ void attitu_kernel(const float* __restrict__ ex1, const float* __restrict__ im1,
                              const float* __restrict__ w11, const float* __restrict__ b11,
                              const float* __restrict__ w12, const float* __restrict__ b12,
                              const float* __restrict__ w21, const float* __restrict__ b21,
                              const float* __restrict__ w22, const float* __restrict__ b22,
                              float* __restrict__ t_ex, float* __restrict__ t_im, int nnodes) {
    int g    = blockIdx.x * blockDim.x + threadIdx.x;
    int node = g >> 5;
    int lane = g & 31;
    if (node >= nnodes) return;
    const float* e1 = ex1 + (size_t)node * DD;
    const float* e2 = im1 + (size_t)node * DD;
    float a0 = e1[lane], a1 = e1[lane + 32];
    float c0 = e2[lane], c1 = e2[lane + 32];
    float p11 = a0 * w11[lane] + a1 * w11[lane + 32];
    float p12 = c0 * w12[lane] + c1 * w12[lane + 32];
    float p21 = a0 * w21[lane] + a1 * w21[lane + 32];
    float p22 = c0 * w22[lane] + c1 * w22[lane + 32];
    #pragma unroll
    for (int o = 16; o > 0; o >>= 1) {
        p11 += __shfl_xor_sync(0xFFFFFFFF, p11, o);
        p12 += __shfl_xor_sync(0xFFFFFFFF, p12, o);
        p21 += __shfl_xor_sync(0xFFFFFFFF, p21, o);
        p22 += __shfl_xor_sync(0xFFFFFFFF, p22, o);
    }
    float l0 = p11 + b11[0], l1 = p12 + b12[0];
    float m = fmaxf(l0, l1);
    float q0 = expf(l0 - m), q1 = expf(l1 - m);
    float inv = 1.0f / (q0 + q1);
    float s0 = q0 * inv, s1 = q1 * inv;
    t_ex[(size_t)node * DD + lane]      = s0 * a0 + s1 * c0;
    t_ex[(size_t)node * DD + lane + 32] = s0 * a1 + s1 * c1;
    float u0 = p21 + b21[0], u1 = p22 + b22[0];
    float m2 = fmaxf(u0, u1);
    float r0 = expf(u0 - m2), r1 = expf(u1 - m2);
    float inv2 = 1.0f / (r0 + r1);
    float t0 = r0 * inv2, t1 = r1 * inv2;
    t_im[(size_t)node * DD + lane]      = t0 * a0 + t1 * c0;
    t_im[(size_t)node * DD + lane + 32] = t0 * a1 + t1 * c1;
}

// ---------------- fused layer-2: out = x1 + t@root2 + b2 + sum_r mean_r(t) @ W2[r] ------
// One block per 64-dst tile. For each r: build A-tile by gather-mean from t (L2-resident),
// load W2[r], GEMM-accumulate. Final pass uses t itself against root2.
__global__ void l2_fused(const float* __restrict__ t, const int* __restrict__ ssrc,
                         const int* __restrict__ offs,
                         const float* __restrict__ W2, const float* __restrict__ root2,
                         const float* __restrict__ b2, const float* __restrict__ x1,
                         float* __restrict__ out, int R, int E) {
    __shared__ float As[64][68];   // stride 68 floats: 16B-aligned rows, bank-spread
    __shared__ float Bs[64][64];
    int row0 = blockIdx.x * 64;
    int tid  = threadIdx.x;
    int tx = tid & 15, ty = tid >> 4;
    int arow = tid >> 2;           // 0..63: dst row this thread gathers for
    int q    = tid & 3;            // quarter of the 64-float row (16 floats)
    int d_g  = row0 + arow;

    float acc[4][4];
    #pragma unroll
    for (int i = 0; i < 4; i++)
        #pragma unroll
        for (int j = 0; j < 4; j++) acc[i][j] = 0.0f;

    for (int r = 0; r <= R; r++) {
        // ---- load B tile ----
        const float* B = (r < R) ? (W2 + (size_t)r * 4096) : root2;
        #pragma unroll
        for (int i = 0; i < 4; i++) {
            int f = tid + i * 256;             // float4 index into 64x64
            int rr = f >> 4, c4 = f & 15;
            reinterpret_cast<float4*>(&Bs[rr][0])[c4] =
                reinterpret_cast<const float4*>(B)[f];
        }
        // ---- build A tile ----
        float4 a0 = make_float4(0.f,0.f,0.f,0.f), a1 = a0, a2 = a0, a3 = a0;
        if (d_g < NN) {
            if (r < R) {
                int key = d_g * R + r;
                int beg = offs[key];
                int end = (key + 1 < NN * R) ? offs[key + 1] : E;
                for (int e = beg; e < end; e++) {
                    const float4* trow = reinterpret_cast<const float4*>(t)
                                       + (size_t)ssrc[e] * 16 + q * 4;
                    float4 v0 = trow[0], v1 = trow[1], v2 = trow[2], v3 = trow[3];
                    a0.x += v0.x; a0.y += v0.y; a0.z += v0.z; a0.w += v0.w;
                    a1.x += v1.x; a1.y += v1.y; a1.z += v1.z; a1.w += v1.w;
                    a2.x += v2.x; a2.y += v2.y; a2.z += v2.z; a2.w += v2.w;
                    a3.x += v3.x; a3.y += v3.y; a3.z += v3.z; a3.w += v3.w;
                }
                if (end > beg) {
                    float inv = 1.0f / (float)(end - beg);
                    a0.x*=inv; a0.y*=inv; a0.z*=inv; a0.w*=inv;
                    a1.x*=inv; a1.y*=inv; a1.z*=inv; a1.w*=inv;
                    a2.x*=inv; a2.y*=inv; a2.z*=inv; a2.w*=inv;
                    a3.x*=inv; a3.y*=inv; a3.z*=inv; a3.w*=inv;
                }
            } else {
                const float4* trow = reinterpret_cast<const float4*>(t)
                                   + (size_t)d_g * 16 + q * 4;
                a0 = trow[0]; a1 = trow[1]; a2 = trow[2]; a3 = trow[3];
            }
        }
        {
            float4* dstp = reinterpret_cast<float4*>(&As[arow][0]) + q * 4;
            dstp[0] = a0; dstp[1] = a1; dstp[2] = a2; dstp[3] = a3;
        }
        __syncthreads();
        // ---- GEMM accumulate: 64x64 tile, 4x4 per thread ----
        #pragma unroll 4
        for (int k = 0; k < 64; k++) {
            float b0 = Bs[k][tx * 4 + 0];
            float b1 = Bs[k][tx * 4 + 1];
            float b2v = Bs[k][tx * 4 + 2];
            float b3 = Bs[k][tx * 4 + 3];
            #pragma unroll
            for (int i = 0; i < 4; i++) {
                float a = As[ty * 4 + i][k];
                acc[i][0] += a * b0;
                acc[i][1] += a * b1;
                acc[i][2] += a * b2v;
                acc[i][3] += a * b3;
            }
        }
        __syncthreads();
    }
    // ---- epilogue: + b2 + x1 ----
    #pragma unroll
    for (int i = 0; i < 4; i++) {
        int gr = row0 + ty * 4 + i;
        if (gr >= NN) continue;
        #pragma unroll
        for (int j = 0; j < 4; j++) {
            int c = tx * 4 + j;
            out[(size_t)gr * 64 + c] = acc[i][j] + b2[c] + x1[(size_t)gr * 64 + c];
        }
    }
}

// ---------------- unified GEMM: C[N,64] = epi( sum_kb A(kb)[N,64] @ B(kb)[64,64] ) ------
__global__ void gemm_uni(const float* __restrict__ A0, int stride0, int kbn0,
                         const float* __restrict__ A1, int stride1, int kbn,
                         const float* __restrict__ B0, const float* __restrict__ B1,
                         const float* __restrict__ bias, const float* __restrict__ add,
                         int leaky, float* __restrict__ C, int nrows) {
    __shared__ float As[128][64];
    __shared__ float Bs[64][64];
    int row0 = blockIdx.x * 128;
    int tid  = threadIdx.x;
    int tx = tid & 15, ty = tid >> 4;
    float acc[8][4];
    #pragma unroll
    for (int i = 0; i < 8; i++)
        #pragma unroll
        for (int j = 0; j < 4; j++) acc[i][j] = 0.0f;

    for (int kb = 0; kb < kbn; kb++) {
        const float* A; int astr; const float* B;
        if (kb < kbn0) { A = A0 + kb * 64;          astr = stride0; B = B0 + (size_t)kb * 4096; }
        else           { A = A1 + (kb - kbn0) * 64; astr = stride1; B = B1 + (size_t)(kb - kbn0) * 4096; }
        #pragma unroll
        for (int i = 0; i < 8; i++) {
            int f = tid + i * 256;
            int rr = f >> 4, c4 = f & 15;
            int gr = row0 + rr;
            float4 v = make_float4(0.f, 0.f, 0.f, 0.f);
            if (gr < nrows)
                v = *reinterpret_cast<const float4*>(A + (size_t)gr * astr + c4 * 4);
            *reinterpret_cast<float4*>(&As[rr][c4 * 4]) = v;
        }
        #pragma unroll
        for (int i = 0; i < 4; i++) {
            int f = tid + i * 256;
            int rr = f >> 4, c4 = f & 15;
            float4 v = *reinterpret_cast<const float4*>(B + rr * 64 + c4 * 4);
            *reinterpret_cast<float4*>(&Bs[rr][c4 * 4]) = v;
        }
        __syncthreads();
        #pragma unroll 4
        for (int k = 0; k < 64; k++) {
            float b0 = Bs[k][tx * 4 + 0];
            float b1 = Bs[k][tx * 4 + 1];
            float b2 = Bs[k][tx * 4 + 2];
            float b3 = Bs[k][tx * 4 + 3];
            #pragma unroll
            for (int i = 0; i < 8; i++) {
                float a = As[ty * 8 + i][k];
                acc[i][0] += a * b0;
                acc[i][1] += a * b1;
                acc[i][2] += a * b2;
                acc[i][3] += a * b3;
            }
        }
        __syncthreads();
    }
    #pragma unroll
    for (int i = 0; i < 8; i++) {
        int gr = row0 + ty * 8 + i;
        if (gr >= nrows) continue;
        #pragma unroll
        for (int j = 0; j < 4; j++) {
            int c = tx * 4 + j;
            float v = acc[i][j];
            if (bias) v += bias[c];
            if (add)  v += add[(size_t)gr * 64 + c];
            if (leaky) v = (v > 0.0f) ? v : 0.01f * v;
            C[(size_t)gr * 64 + c] = v;
        }
    }
}

// ---------------- host ----------------
extern "C" void kernel_launch(void* const* d_in, const int* in_sizes, int n_in,
                              void* d_out, int out_size) {
    (void)in_sizes; (void)n_in; (void)out_size;
    const int*   ei_ex   = (const int*)d_in[0];
    const int*   et_ex   = (const int*)d_in[1];
    const int*   ei_im   = (const int*)d_in[2];
    const int*   et_im   = (const int*)d_in[3];
    const float* W1_ex   = (const float*)d_in[4];
    const float* root1_ex= (const float*)d_in[5];
    const float* b1_ex   = (const float*)d_in[6];
    const float* W1_im   = (const float*)d_in[7];
    const float* root1_im= (const float*)d_in[8];
    const float* b1_im   = (const float*)d_in[9];
    const float* W2_ex   = (const float*)d_in[10];
    const float* root2_ex= (const float*)d_in[11];
    const float* b2_ex   = (const float*)d_in[12];
    const float* W2_im   = (const float*)d_in[13];
    const float* root2_im= (const float*)d_in[14];
    const float* b2_im   = (const float*)d_in[15];
    const float* aw11 = (const float*)d_in[16]; const float* ab11 = (const float*)d_in[17];
    const float* aw12 = (const float*)d_in[18]; const float* ab12 = (const float*)d_in[19];
    const float* aw21 = (const float*)d_in[20]; const float* ab21 = (const float*)d_in[21];
    const float* aw22 = (const float*)d_in[22]; const float* ab22 = (const float*)d_in[23];
    const float* agg_W1 = (const float*)d_in[24]; const float* agg_b1 = (const float*)d_in[25];
    const float* agg_W2 = (const float*)d_in[26]; const float* agg_b2 = (const float*)d_in[27];
    float* out = (float*)d_out;

    const int* src_ex = ei_ex;
    const int* dst_ex = ei_ex + EEX;
    const int* src_im = ei_im;
    const int* dst_im = ei_im + EIM;

    void *p_cnt_ex, *p_cnt_im, *p_offs_ex, *p_offs_im, *p_cur_ex, *p_cur_im,
         *p_bs_ex, *p_bs_im, *p_bs2_ex, *p_bs2_im, *p_ssrc_ex, *p_ssrc_im,
         *p_ex_x1, *p_im_x1, *p_t_ex, *p_t_im, *p_ex_sum, *p_im_sum, *p_hidden;
    cudaGetSymbolAddress(&p_cnt_ex, g_cnt_ex);
    cudaGetSymbolAddress(&p_cnt_im, g_cnt_im);
    cudaGetSymbolAddress(&p_offs_ex, g_offs_ex);
    cudaGetSymbolAddress(&p_offs_im, g_offs_im);
    cudaGetSymbolAddress(&p_cur_ex, g_cur_ex);
    cudaGetSymbolAddress(&p_cur_im, g_cur_im);
    cudaGetSymbolAddress(&p_bs_ex, g_bs_ex);
    cudaGetSymbolAddress(&p_bs_im, g_bs_im);
    cudaGetSymbolAddress(&p_bs2_ex, g_bs2_ex);
    cudaGetSymbolAddress(&p_bs2_im, g_bs2_im);
    cudaGetSymbolAddress(&p_ssrc_ex, g_ssrc_ex);
    cudaGetSymbolAddress(&p_ssrc_im, g_ssrc_im);
    cudaGetSymbolAddress(&p_ex_x1, g_ex_x1);
    cudaGetSymbolAddress(&p_im_x1, g_im_x1);
    cudaGetSymbolAddress(&p_t_ex, g_t_ex);
    cudaGetSymbolAddress(&p_t_im, g_t_im);
    cudaGetSymbolAddress(&p_ex_sum, g_ex_sum);
    cudaGetSymbolAddress(&p_im_sum, g_im_sum);
    cudaGetSymbolAddress(&p_hidden, g_hidden);

    const int NRE = NN * REX;                 // 800000
    const int NRI = NN * RIM;                 // 400000
    const int NBE = (NRE + 1023) / 1024;      // 782
    const int NBI = (NRI + 1023) / 1024;      // 391

    // 1) counts
    cudaMemsetAsync(p_cnt_ex, 0, sizeof(int) * NRE);
    cudaMemsetAsync(p_cnt_im, 0, sizeof(int) * NRI);
    count_kernel<<<(EEX + 255) / 256, 256>>>(dst_ex, et_ex, EEX, (int*)p_cnt_ex, REX);
    count_kernel<<<(EIM + 255) / 256, 256>>>(dst_im, et_im, EIM, (int*)p_cnt_im, RIM);

    // 2) exclusive scan -> segment offsets
    scan1<<<NBE, 256>>>((const int*)p_cnt_ex, NRE, (int*)p_offs_ex, (int*)p_bs_ex);
    scan1<<<NBI, 256>>>((const int*)p_cnt_im, NRI, (int*)p_offs_im, (int*)p_bs_im);
    scan1<<<1, 256>>>((const int*)p_bs_ex, NBE, (int*)p_bs2_ex, nullptr);
    scan1<<<1, 256>>>((const int*)p_bs_im, NBI, (int*)p_bs2_im, nullptr);
    scan_add4<<<NBE, 256>>>((int*)p_offs_ex, (const int*)p_bs2_ex, NRE);
    scan_add4<<<NBI, 256>>>((int*)p_offs_im, (const int*)p_bs2_im, NRI);

    // 3) counting sort: group src by (dst, r)
    cudaMemcpyAsync(p_cur_ex, p_offs_ex, sizeof(int) * NRE, cudaMemcpyDeviceToDevice);
    cudaMemcpyAsync(p_cur_im, p_offs_im, sizeof(int) * NRI, cudaMemcpyDeviceToDevice);
    sort_kernel<<<(EEX + 255) / 256, 256>>>(src_ex, dst_ex, et_ex, EEX, REX,
                                            (int*)p_cur_ex, (int*)p_ssrc_ex);
    sort_kernel<<<(EIM + 255) / 256, 256>>>(src_im, dst_im, et_im, EIM, RIM,
                                            (int*)p_cur_im, (int*)p_ssrc_im);

    // 4) layer-1 (owner-write aggregation)
    agg_l1<<<(NN * 16 + 255) / 256, 256>>>(W1_ex, (const int*)p_ssrc_ex, (const int*)p_offs_ex,
                                           root1_ex, b1_ex, (float*)p_ex_x1, REX, EEX);
    agg_l1<<<(NN * 16 + 255) / 256, 256>>>(W1_im, (const int*)p_ssrc_im, (const int*)p_offs_im,
                                           root1_im, b1_im, (float*)p_im_x1, RIM, EIM);

    // 5) ATTITU fusion
    attitu_kernel<<<(NN * 32 + 255) / 256, 256>>>((const float*)p_ex_x1, (const float*)p_im_x1,
                                                  aw11, ab11, aw12, ab12, aw21, ab21, aw22, ab22,
                                                  (float*)p_t_ex, (float*)p_t_im, NN);

    const int tiles64 = (NN + 63) / 64;       // 1563

    // 6) fused layer-2: gather-mean + GEMM + root path + epilogue, no h staging
    l2_fused<<<tiles64, 256>>>((const float*)p_t_ex, (const int*)p_ssrc_ex,
                               (const int*)p_offs_ex, W2_ex, root2_ex, b2_ex,
                               (const float*)p_ex_x1, (float*)p_ex_sum, REX, EEX);
    l2_fused<<<tiles64, 256>>>((const float*)p_t_im, (const int*)p_ssrc_im,
                               (const int*)p_offs_im, W2_im, root2_im, b2_im,
                               (const float*)p_im_x1, (float*)p_im_sum, RIM, EIM);

    const int tiles128 = (NN + 127) / 128;    // 782

    // 7) hidden = leaky_relu([ex_sum | im_sum] @ agg_W1 + agg_b1)
    gemm_uni<<<tiles128, 256>>>((const float*)p_ex_sum, 64, 1,
                                (const float*)p_im_sum, 64, 2,
                                agg_W1, agg_W1 + 64 * 64, agg_b1, nullptr,
                                1, (float*)p_hidden, NN);

    // 8) out = hidden @ agg_W2 + agg_b2
    gemm_uni<<<tiles128, 256>>>((const float*)p_hidden, 64, 1,
                                nullptr, 0, 1,
                                agg_W2, nullptr, agg_b2, nullptr,
                                0, out, NN);
}